// round 15
// baseline (speedup 1.0000x reference)
#include <cuda_runtime.h>

// filtfilt (butter(4,0.2)) over (8,64,48000) fp32 — fused smem kernel, v13.
// vs v12 (39.0us): NSEG 8->9 to fix wave quantization (4096 blocks = 3.37
// waves at 8 blocks/SM on 152 SMs, 37%-full tail; 4608 blocks = 3.79 waves,
// 79%-full tail). SEGC=5340, L=22, HALO=45 (halo must cover chunk-overshoot
// + W for every backward warmup window — verified for all 3 block classes).
// Everything else identical: all-bulk-DMA I/O, W=32 FIR warmup, float2
// chunks (stride 11 -> conflict-free), 8 blocks/SM, 32 regs.

#define T_LEN  48000
#define PADL   15
#define TP     (T_LEN + 2 * PADL)   // 48030
#define ROWS   512
#define NSEG   9
#define SEGC   5340                 // 9*5340 = 48060 >= TP; mult of 4
#define NTHR   256
#define L      22                   // chunk per thread; float2 stride 11: CF
#define W      32                   // warmup depth (FIR truncation)
#define HALO   45                   // covers overshoot(<=L-1) + W for bwd warmup
#define BODY   (NTHR * L)           // 5632 >= SEGC + 2*HALO = 5430
#define SMEMN  (W + BODY + W)       // 5696 floats
#define SMEMF  (SMEMN * 4)          // 22784 B
#define SMEMB  (SMEMF + 16)         // + mbarrier -> 8 blocks/SM

// Per-class constants (sg0: e0=-13; sg8: e0=42675; interior: e0=core0-45)
#define EXTI   5430                 // interior valid body samples
#define EXT0   5400                 // sg0 (bulk covers bi [28,5400))
#define EXT8   5355                 // sg8 (p through TP-1)
#define LB_I   21712                // interior bulk load: 5428 elems
#define LB_E0  21488                // sg0 bulk load: 5372 elems
#define LB_E8  21360                // sg8 bulk load: 5340 elems (x[42660..48000))
#define SB_I   21344                // interior bulk store: 5336 elems
#define SB_0   21296                // sg0 bulk store: 5324 elems
#define SB_8   21168                // sg8 bulk store: 5292 elems

#define B0c 0.004824343357716228f
#define B1c 0.019297373430864913f
#define B2c 0.02894606014629737f
#define B3c 0.019297373430864913f
#define B4c 0.004824343357716228f
#define A1c (-2.369513007182038f)
#define A2c ( 2.3139884144006455f)
#define A3c (-1.0546654058785672f)
#define A4c ( 0.18737949236818502f)

// Impulse response h[k] of the IIR, computed at compile time.
struct HArr { float h[W]; };
__host__ __device__ constexpr HArr make_h() {
    HArr r{};
    double hd[W] = {};
    const double b[5] = {0.004824343357716228, 0.019297373430864913,
                         0.02894606014629737, 0.019297373430864913,
                         0.004824343357716228};
    const double a[4] = {-2.369513007182038, 2.3139884144006455,
                         -1.0546654058785672, 0.18737949236818502};
    for (int k = 0; k < W; ++k) {
        double v = (k < 5) ? b[k] : 0.0;
        for (int j = 0; j < 4; ++j)
            if (k - 1 - j >= 0) v -= a[j] * hd[k - 1 - j];
        hd[k] = v;
        r.h[k] = (float)v;
    }
    return r;
}

struct St { float w0, w1, w2, w3, s1, s2, s3, s4; };

// Truncated-FIR warmup over W samples in [base, base+W) (8B-aligned).
template <bool REV>
__device__ __forceinline__ St fir_warmup(const float* base) {
    constexpr HArr HCk = make_h();
    const float2* p2 = reinterpret_cast<const float2*>(base);
    St st = {0.f, 0.f, 0.f, 0.f, 0.f, 0.f, 0.f, 0.f};
#pragma unroll
    for (int q = 0; q < W / 2; ++q) {
        float2 v = p2[q];
#pragma unroll
        for (int e = 0; e < 2; ++e) {
            const int j = 2 * q + e;
            const int i = REV ? j : (W - 1 - j);
            const float val = e ? v.y : v.x;
            st.s1 = fmaf(HCk.h[i], val, st.s1);
            if (i >= 1) st.s2 = fmaf(HCk.h[i - 1], val, st.s2);
            if (i >= 2) st.s3 = fmaf(HCk.h[i - 2], val, st.s3);
            if (i >= 3) st.s4 = fmaf(HCk.h[i - 3], val, st.s4);
            if (i == 0) st.w0 = val;
            if (i == 1) st.w1 = val;
            if (i == 2) st.w2 = val;
            if (i == 3) st.w3 = val;
        }
    }
    return st;
}

#define IIR_STEP(xn, yout)                                   \
    do {                                                     \
        float f_ = B0c * (xn);                               \
        f_ = fmaf(B1c, w0_, f_);                             \
        f_ = fmaf(B2c, w1_, f_);                             \
        f_ = fmaf(B3c, w2_, f_);                             \
        f_ = fmaf(B4c, w3_, f_);                             \
        f_ = fmaf(-A2c, s2_, f_);                            \
        f_ = fmaf(-A3c, s3_, f_);                            \
        f_ = fmaf(-A4c, s4_, f_);                            \
        (yout) = fmaf(-A1c, s1_, f_);                        \
        w3_ = w2_; w2_ = w1_; w1_ = w0_; w0_ = (xn);         \
        s4_ = s3_; s3_ = s2_; s2_ = s1_; s1_ = (yout);       \
    } while (0)

#define ST_UNPACK(st)                                         \
    float w0_ = st.w0, w1_ = st.w1, w2_ = st.w2, w3_ = st.w3, \
          s1_ = st.s1, s2_ = st.s2, s3_ = st.s3, s4_ = st.s4

__device__ __forceinline__ void mbar_wait0(unsigned mbar) {
    asm volatile(
        "{\n\t.reg .pred P%=;\n"
        "LW%=:\n\t"
        "mbarrier.try_wait.parity.acquire.cta.shared::cta.b64 P%=, [%0], 0;\n\t"
        "@!P%= bra LW%=;\n\t}"
        :: "r"(mbar) : "memory");
}

__global__ void __launch_bounds__(NTHR, 8)
fused_filtfilt(const float* __restrict__ x, float* __restrict__ out) {
    extern __shared__ float smem_raw[];
    float* xsp = smem_raw + W;               // body coord 0 (128B-aligned)
    const int tid = threadIdx.x;
    const int blk = blockIdx.x;
    const int r = blk / NSEG;
    const int sg = blk - r * NSEG;
    const float* __restrict__ xr = x + (size_t)r * T_LEN;
    float* __restrict__ outr = out + (size_t)r * T_LEN;

    const bool is0 = (sg == 0);
    const bool is8 = (sg == NSEG - 1);
    const int core0 = sg * SEGC;
    const int ext_len = is0 ? EXT0 : (is8 ? EXT8 : EXTI);

    // ============ Load phase (all classes: bulk + few scalars) ============
    {
        const unsigned mbar = (unsigned)__cvta_generic_to_shared(
            reinterpret_cast<char*>(smem_raw) + SMEMF);
        const float* src = is0 ? xr : (xr + (core0 - HALO - PADL)); // 16B-aligned
        const int dst_bi = is0 ? 28 : 0;                            // 16B-aligned
        const unsigned lbytes = is0 ? LB_E0 : (is8 ? LB_E8 : LB_I);
        if (tid == 0) {
            asm volatile("mbarrier.init.shared.b64 [%0], 1;" :: "r"(mbar) : "memory");
            asm volatile("mbarrier.arrive.expect_tx.shared.b64 _, [%0], %1;"
                         :: "r"(mbar), "r"(lbytes) : "memory");
            const unsigned dst = (unsigned)__cvta_generic_to_shared(xsp + dst_bi);
            asm volatile(
                "cp.async.bulk.shared::cta.global.mbarrier::complete_tx::bytes "
                "[%0], [%1], %2, [%3];"
                :: "r"(dst), "l"(src), "r"(lbytes), "r"(mbar) : "memory");
        }
        // zeros + reflected/tail scalars, concurrent with DMA (disjoint regions)
        for (int i = tid; i < W; i += NTHR) smem_raw[i] = 0.f;   // leading apron
        for (int i = W + ext_len + tid; i < SMEMN; i += NTHR) smem_raw[i] = 0.f;
        if (is0) {
            if (tid < 13) xsp[tid] = 0.f;                        // p = -13..-1
            else if (tid < 28)                                   // p = 0..14 reflect
                xsp[tid] = 2.f * xr[0] - xr[27 - tid];
        } else if (is8) {
            if (tid < 15)                                        // p = 48015..48029
                xsp[5340 + tid] = 2.f * xr[T_LEN - 1] - xr[47997 - tid];
        } else {
            if (tid < 2) xsp[5428 + tid] = src[5428 + tid];      // bulk tail
        }
        __syncthreads();                 // mbar init + scalar writes visible
        mbar_wait0(mbar);
    }

    const int ps = tid * L;

    // ============ Forward pass (in place, float2) ============
    {
        St st = fir_warmup<false>(xsp + ps - W);
        ST_UNPACK(st);
        __syncthreads();                 // cross-chunk reads before writes
        float2* cp2 = reinterpret_cast<float2*>(xsp + ps);
        float y0, y1;
#pragma unroll
        for (int q = 0; q < L / 2; ++q) {
            float2 v = cp2[q];
            IIR_STEP(v.x, y0);
            IIR_STEP(v.y, y1);
            cp2[q] = make_float2(y0, y1);
        }
        // Self-zero beyond valid extent: backward recursion must see exact
        // zeros past the padded row end (reference zero-init semantics).
        if (ps + L > ext_len) {
            for (int t = max(ps, ext_len); t < ps + L; ++t) xsp[t] = 0.f;
        }
    }
    __syncthreads();

    // ============ Backward pass (in place, reversed, float2) ============
    {
        St st = fir_warmup<true>(xsp + ps + L);
        ST_UNPACK(st);
        __syncthreads();
        float2* cp2 = reinterpret_cast<float2*>(xsp + ps);
        float y0, y1;
#pragma unroll
        for (int q = L / 2 - 1; q >= 0; --q) {
            float2 v = cp2[q];
            IIR_STEP(v.y, y1);           // higher address first
            IIR_STEP(v.x, y0);
            cp2[q] = make_float2(y0, y1);
        }
    }
    __syncthreads();

    // ============ Store phase (all classes: scalars + bulk) ============
    if (is0) {
        // stored p in [15, 5340): out[0..5325); bi = p + 13
        if (tid == 1) outr[5324] = xsp[5352];                // p = 5339
        if (tid == 0) {
            const unsigned srcs = (unsigned)__cvta_generic_to_shared(xsp + 28);
            asm volatile("fence.proxy.async;" ::: "memory");
            asm volatile(
                "cp.async.bulk.global.shared::cta.bulk_group [%0], [%1], %2;"
                :: "l"(outr), "r"(srcs), "r"((unsigned)SB_0) : "memory");
            asm volatile("cp.async.bulk.commit_group;" ::: "memory");
            asm volatile("cp.async.bulk.wait_group 0;" ::: "memory");
        }
    } else {
        // head p = core0..core0+2 ; interior tail p = core0+SEGC-1
        if (tid < 3) outr[core0 - PADL + tid] = xsp[HALO + tid];
        if (!is8 && tid == 3) outr[core0 + SEGC - 1 - PADL] = xsp[HALO + SEGC - 1];
        if (tid == 0) {
            const unsigned srcs = (unsigned)__cvta_generic_to_shared(xsp + HALO + 3);
            float* dst = outr + (core0 + 3 - PADL);
            const unsigned sbytes = is8 ? SB_8 : SB_I;
            asm volatile("fence.proxy.async;" ::: "memory");
            asm volatile(
                "cp.async.bulk.global.shared::cta.bulk_group [%0], [%1], %2;"
                :: "l"(dst), "r"(srcs), "r"(sbytes) : "memory");
            asm volatile("cp.async.bulk.commit_group;" ::: "memory");
            asm volatile("cp.async.bulk.wait_group 0;" ::: "memory");
        }
    }
}

extern "C" void kernel_launch(void* const* d_in, const int* in_sizes, int n_in,
                              void* d_out, int out_size) {
    const float* x = (const float*)d_in[0];
    float* out = (float*)d_out;
    cudaFuncSetAttribute(fused_filtfilt,
                         cudaFuncAttributeMaxDynamicSharedMemorySize, SMEMB);
    fused_filtfilt<<<ROWS * NSEG, NTHR, SMEMB>>>(x, out);
}

// round 17
// speedup vs baseline: 1.0181x; 1.0181x over previous
#include <cuda_runtime.h>

// filtfilt (butter(4,0.2)) over (8,64,48000) fp32 — fused smem kernel, v15.
// = v14 (float4 smem paths, L=28) with the in-place macro aliasing FIXED:
// IIR_STEP(v.x, v.x) let the macro's trailing "w0_ = xn" capture the OUTPUT
// (xn and yout were the same lvalue), corrupting the FIR window -> rel_err
// 1.16. Outputs now go to distinct temporaries, vector written after.
// Seam decay audit for L=28/HALO=45: truncated warmup taps sit at depth>=18
// and decay a further 0.7956^27 before any stored sample (~3e-5) — safe.

#define T_LEN  48000
#define PADL   15
#define TP     (T_LEN + 2 * PADL)   // 48030
#define ROWS   512
#define NSEG   8
#define SEGC   6004                 // 8*6004 = 48032 >= TP
#define NTHR   256
#define L      28                   // chunk per thread (mult 4, CF float4)
#define W      32                   // warmup depth (FIR truncation)
#define HALO   45                   // interior halo; e0 == 3 (mod 4)
#define BODY   (NTHR * L)           // 7168 >= 6094
#define SMEMN  (W + BODY + W)       // 7232 floats
#define SMEMF  (SMEMN * 4)          // 28928 B
#define SMEMB  (SMEMF + 16)         // + mbarrier -> 28944 B (8 blocks/SM)

// Per-class constants (identical to v12)
#define EXTI   6094                 // interior valid body samples
#define EXT0   6063                 // sg0  (e0=-13)
#define EXT7   6047                 // sg7  (e0=41983)
#define LB_I   24368                // interior bulk load: 6092 elems
#define LB_E   24128                // edge bulk load: 6032 elems
#define SB_I   24000                // interior bulk store: 6000 elems
#define SB_0   23952                // sg0 bulk store: 5988 elems
#define SB_7   23936                // sg7 bulk store: 5984 elems

#define B0c 0.004824343357716228f
#define B1c 0.019297373430864913f
#define B2c 0.02894606014629737f
#define B3c 0.019297373430864913f
#define B4c 0.004824343357716228f
#define A1c (-2.369513007182038f)
#define A2c ( 2.3139884144006455f)
#define A3c (-1.0546654058785672f)
#define A4c ( 0.18737949236818502f)

// Impulse response h[k] of the IIR, computed at compile time.
struct HArr { float h[W]; };
__host__ __device__ constexpr HArr make_h() {
    HArr r{};
    double hd[W] = {};
    const double b[5] = {0.004824343357716228, 0.019297373430864913,
                         0.02894606014629737, 0.019297373430864913,
                         0.004824343357716228};
    const double a[4] = {-2.369513007182038, 2.3139884144006455,
                         -1.0546654058785672, 0.18737949236818502};
    for (int k = 0; k < W; ++k) {
        double v = (k < 5) ? b[k] : 0.0;
        for (int j = 0; j < 4; ++j)
            if (k - 1 - j >= 0) v -= a[j] * hd[k - 1 - j];
        hd[k] = v;
        r.h[k] = (float)v;
    }
    return r;
}

struct St { float w0, w1, w2, w3, s1, s2, s3, s4; };

// Truncated-FIR warmup over W samples in [base, base+W) (16B-aligned).
template <bool REV>
__device__ __forceinline__ St fir_warmup(const float* base) {
    constexpr HArr HCk = make_h();
    const float4* p4 = reinterpret_cast<const float4*>(base);
    St st = {0.f, 0.f, 0.f, 0.f, 0.f, 0.f, 0.f, 0.f};
#pragma unroll
    for (int q = 0; q < W / 4; ++q) {
        float4 v = p4[q];
#pragma unroll
        for (int e = 0; e < 4; ++e) {
            const int j = 4 * q + e;
            const int i = REV ? j : (W - 1 - j);
            const float val = (e == 0) ? v.x : (e == 1) ? v.y : (e == 2) ? v.z : v.w;
            st.s1 = fmaf(HCk.h[i], val, st.s1);
            if (i >= 1) st.s2 = fmaf(HCk.h[i - 1], val, st.s2);
            if (i >= 2) st.s3 = fmaf(HCk.h[i - 2], val, st.s3);
            if (i >= 3) st.s4 = fmaf(HCk.h[i - 3], val, st.s4);
            if (i == 0) st.w0 = val;
            if (i == 1) st.w1 = val;
            if (i == 2) st.w2 = val;
            if (i == 3) st.w3 = val;
        }
    }
    return st;
}

// NOTE: xn and yout MUST be distinct lvalues (w0_ = xn runs after yout write).
#define IIR_STEP(xn, yout)                                   \
    do {                                                     \
        float f_ = B0c * (xn);                               \
        f_ = fmaf(B1c, w0_, f_);                             \
        f_ = fmaf(B2c, w1_, f_);                             \
        f_ = fmaf(B3c, w2_, f_);                             \
        f_ = fmaf(B4c, w3_, f_);                             \
        f_ = fmaf(-A2c, s2_, f_);                            \
        f_ = fmaf(-A3c, s3_, f_);                            \
        f_ = fmaf(-A4c, s4_, f_);                            \
        (yout) = fmaf(-A1c, s1_, f_);                        \
        w3_ = w2_; w2_ = w1_; w1_ = w0_; w0_ = (xn);         \
        s4_ = s3_; s3_ = s2_; s2_ = s1_; s1_ = (yout);       \
    } while (0)

#define ST_UNPACK(st)                                         \
    float w0_ = st.w0, w1_ = st.w1, w2_ = st.w2, w3_ = st.w3, \
          s1_ = st.s1, s2_ = st.s2, s3_ = st.s3, s4_ = st.s4

__device__ __forceinline__ void mbar_wait0(unsigned mbar) {
    asm volatile(
        "{\n\t.reg .pred P%=;\n"
        "LW%=:\n\t"
        "mbarrier.try_wait.parity.acquire.cta.shared::cta.b64 P%=, [%0], 0;\n\t"
        "@!P%= bra LW%=;\n\t}"
        :: "r"(mbar) : "memory");
}

__global__ void __launch_bounds__(NTHR, 8)
fused_filtfilt(const float* __restrict__ x, float* __restrict__ out) {
    extern __shared__ float smem_raw[];
    float* xsp = smem_raw + W;               // body coord 0 (128B-aligned)
    const int tid = threadIdx.x;
    const int blk = blockIdx.x;
    const int r = blk >> 3;
    const int sg = blk & 7;
    const float* __restrict__ xr = x + (size_t)r * T_LEN;
    float* __restrict__ outr = out + (size_t)r * T_LEN;

    const bool is0 = (sg == 0);
    const bool is7 = (sg == NSEG - 1);
    const int core0 = sg * SEGC;
    const int e0 = is0 ? -13 : core0 - HALO;
    const int ext_len = is0 ? EXT0 : (is7 ? EXT7 : EXTI);

    // ============ Load phase (all classes: bulk + few scalars) ============
    {
        const unsigned mbar = (unsigned)__cvta_generic_to_shared(
            reinterpret_cast<char*>(smem_raw) + SMEMF);
        const float* src = is0 ? xr : (xr + (e0 - PADL));   // 16B-aligned
        const int dst_bi = is0 ? 28 : 0;                    // 16B-aligned dst
        const unsigned lbytes = (is0 || is7) ? LB_E : LB_I;
        if (tid == 0) {
            asm volatile("mbarrier.init.shared.b64 [%0], 1;" :: "r"(mbar) : "memory");
            asm volatile("mbarrier.arrive.expect_tx.shared.b64 _, [%0], %1;"
                         :: "r"(mbar), "r"(lbytes) : "memory");
            const unsigned dst = (unsigned)__cvta_generic_to_shared(xsp + dst_bi);
            asm volatile(
                "cp.async.bulk.shared::cta.global.mbarrier::complete_tx::bytes "
                "[%0], [%1], %2, [%3];"
                :: "r"(dst), "l"(src), "r"(lbytes), "r"(mbar) : "memory");
        }
        // zeros + reflected scalars, concurrent with DMA (disjoint regions)
        for (int i = tid; i < W; i += NTHR) smem_raw[i] = 0.f;   // leading apron
        for (int i = W + ext_len + tid; i < SMEMN; i += NTHR) smem_raw[i] = 0.f;
        if (is0) {
            if (tid < 13) xsp[tid] = 0.f;                        // p = -13..-1
            else if (tid < 28)                                   // p = 0..14 reflect
                xsp[tid] = 2.f * xr[0] - xr[27 - tid];
            else if (tid < 31)                                   // bulk tail
                xsp[6060 + (tid - 28)] = xr[6032 + (tid - 28)];
        } else if (is7) {
            if (tid < 15)                                        // p = 48015..48029
                xsp[6032 + tid] = 2.f * xr[T_LEN - 1] - xr[47997 - tid];
        } else {
            if (tid < 2) xsp[6092 + tid] = src[6092 + tid];      // bulk tail
        }
        __syncthreads();                 // mbar init + scalar writes visible
        mbar_wait0(mbar);
    }

    const int ps = tid * L;              // 28*tid: 16B-aligned word index

    // ============ Forward pass (in place, float4) ============
    {
        St st = fir_warmup<false>(xsp + ps - W);
        ST_UNPACK(st);
        __syncthreads();                 // cross-chunk reads before writes
        float4* cp4 = reinterpret_cast<float4*>(xsp + ps);
#pragma unroll
        for (int q = 0; q < L / 4; ++q) {
            float4 v = cp4[q];
            float y0, y1, y2, y3;
            IIR_STEP(v.x, y0);
            IIR_STEP(v.y, y1);
            IIR_STEP(v.z, y2);
            IIR_STEP(v.w, y3);
            cp4[q] = make_float4(y0, y1, y2, y3);
        }
        // Self-zero beyond valid extent: backward recursion must see exact
        // zeros past the padded row end (reference zero-init semantics).
        if (ps + L > ext_len) {
            for (int t = max(ps, ext_len); t < ps + L; ++t) xsp[t] = 0.f;
        }
    }
    __syncthreads();

    // ============ Backward pass (in place, reversed, float4) ============
    {
        St st = fir_warmup<true>(xsp + ps + L);
        ST_UNPACK(st);
        __syncthreads();
        float4* cp4 = reinterpret_cast<float4*>(xsp + ps);
#pragma unroll
        for (int q = L / 4 - 1; q >= 0; --q) {
            float4 v = cp4[q];
            float y0, y1, y2, y3;
            IIR_STEP(v.w, y3);           // higher address first
            IIR_STEP(v.z, y2);
            IIR_STEP(v.y, y1);
            IIR_STEP(v.x, y0);
            cp4[q] = make_float4(y0, y1, y2, y3);
        }
    }
    __syncthreads();

    // ============ Store phase (all classes: scalars + bulk) ============
    if (is0) {
        if (tid == 1) outr[5988] = xsp[6016];                // p = 6003
        if (tid == 0) {
            const unsigned srcs = (unsigned)__cvta_generic_to_shared(xsp + 28);
            asm volatile("fence.proxy.async;" ::: "memory");
            asm volatile(
                "cp.async.bulk.global.shared::cta.bulk_group [%0], [%1], %2;"
                :: "l"(outr), "r"(srcs), "r"((unsigned)SB_0) : "memory");
            asm volatile("cp.async.bulk.commit_group;" ::: "memory");
            asm volatile("cp.async.bulk.wait_group 0;" ::: "memory");
        }
    } else {
        if (tid < 3) outr[core0 - PADL + tid] = xsp[HALO + tid];
        if (!is7 && tid == 3) outr[core0 + SEGC - 1 - PADL] = xsp[HALO + SEGC - 1];
        if (tid == 0) {
            const unsigned srcs = (unsigned)__cvta_generic_to_shared(xsp + HALO + 3);
            float* dst = outr + (core0 + 3 - PADL);
            const unsigned sbytes = is7 ? SB_7 : SB_I;
            asm volatile("fence.proxy.async;" ::: "memory");
            asm volatile(
                "cp.async.bulk.global.shared::cta.bulk_group [%0], [%1], %2;"
                :: "l"(dst), "r"(srcs), "r"(sbytes) : "memory");
            asm volatile("cp.async.bulk.commit_group;" ::: "memory");
            asm volatile("cp.async.bulk.wait_group 0;" ::: "memory");
        }
    }
}

extern "C" void kernel_launch(void* const* d_in, const int* in_sizes, int n_in,
                              void* d_out, int out_size) {
    const float* x = (const float*)d_in[0];
    float* out = (float*)d_out;
    cudaFuncSetAttribute(fused_filtfilt,
                         cudaFuncAttributeMaxDynamicSharedMemorySize, SMEMB);
    fused_filtfilt<<<ROWS * NSEG, NTHR, SMEMB>>>(x, out);
}